// round 9
// baseline (speedup 1.0000x reference)
#include <cuda_runtime.h>
#include <cstdint>
#include <math.h>

#define BATCH 64
#define SEQ   512
#define INSZ  512
#define HSZ   512
#define G4    2048   // 4*HSZ
#define NCTA  128
#define GRP   32     // CTAs per bt-group

// ---------------- scratch (device globals; no allocation allowed) ----------
__device__ float g_xT[(size_t)SEQ * INSZ * BATCH];     // 64MB: x transposed [t][k][b]
__device__ float g_wihT[(size_t)32 * 512 * 32 * 2];    // 4MB: Wih lane-matched [jt][k/4][lane][k%4][2]
__device__ float g_hT[2][HSZ * BATCH];                 // transposed hidden state [j][b]
__device__ unsigned g_cnt4[4][32];                     // per-group monotonic counters

// ---------------- f32x2 packed math helpers (sm_103a) ----------------------
__device__ __forceinline__ unsigned long long pack2(float lo, float hi) {
    unsigned long long r;
    asm("mov.b64 %0, {%1, %2};" : "=l"(r) : "f"(lo), "f"(hi));
    return r;
}
__device__ __forceinline__ void unpack2(unsigned long long v, float& lo, float& hi) {
    asm("mov.b64 {%0, %1}, %2;" : "=f"(lo), "=f"(hi) : "l"(v));
}
__device__ __forceinline__ unsigned long long ffma2(unsigned long long a,
                                                    unsigned long long b,
                                                    unsigned long long c) {
    unsigned long long d;
    asm("fma.rn.f32x2 %0, %1, %2, %3;" : "=l"(d) : "l"(a), "l"(b), "l"(c));
    return d;
}

// ---------------- fast activations (MUFU-based, rel err ~1e-6) -------------
__device__ __forceinline__ float ex2f(float x) {
    float y; asm("ex2.approx.f32 %0, %1;" : "=f"(y) : "f"(x)); return y;
}
__device__ __forceinline__ float rcpf(float x) {
    float y; asm("rcp.approx.f32 %0, %1;" : "=f"(y) : "f"(x)); return y;
}
#define LOG2E 1.4426950408889634f
__device__ __forceinline__ float fast_sigmoid(float x) {
    return rcpf(1.0f + ex2f(-x * LOG2E));
}
__device__ __forceinline__ float fast_tanh(float x) {
    float a = fabsf(x);
    float t = ex2f(-2.0f * LOG2E * a);
    float r = 1.0f - 2.0f * t * rcpf(1.0f + t);
    return copysignf(r, x);
}

// one k of the gate GEMM: 8 batch-pair accumulators x 2 gate-dims
__device__ __forceinline__ void gemm_k(const float* sT, int k, float wA, float wB,
                                       unsigned long long (&accA)[8],
                                       unsigned long long (&accB)[8]) {
    unsigned long long wa = pack2(wA, wA);
    unsigned long long wb = pack2(wB, wB);
    const ulonglong2* hp = (const ulonglong2*)&sT[k * 16];
    ulonglong2 h01 = hp[0], h23 = hp[1], h45 = hp[2], h67 = hp[3];
    accA[0] = ffma2(h01.x, wa, accA[0]); accB[0] = ffma2(h01.x, wb, accB[0]);
    accA[1] = ffma2(h01.y, wa, accA[1]); accB[1] = ffma2(h01.y, wb, accB[1]);
    accA[2] = ffma2(h23.x, wa, accA[2]); accB[2] = ffma2(h23.x, wb, accB[2]);
    accA[3] = ffma2(h23.y, wa, accA[3]); accB[3] = ffma2(h23.y, wb, accB[3]);
    accA[4] = ffma2(h45.x, wa, accA[4]); accB[4] = ffma2(h45.x, wb, accB[4]);
    accA[5] = ffma2(h45.y, wa, accA[5]); accB[5] = ffma2(h45.y, wb, accB[5]);
    accA[6] = ffma2(h67.x, wa, accA[6]); accB[6] = ffma2(h67.x, wb, accB[6]);
    accA[7] = ffma2(h67.y, wa, accA[7]); accB[7] = ffma2(h67.y, wb, accB[7]);
}

// ---------------- prologue 1: transpose x -> g_xT[t][k][b] -----------------
__global__ void wtrans_x(const float* __restrict__ X) {
    size_t gid = (size_t)blockIdx.x * blockDim.x + threadIdx.x;  // 0..16777215
    int t = (int)(gid >> 15);
    int r = (int)(gid & 32767);
    int k = r >> 6;
    int b = r & 63;
    g_xT[gid] = X[((size_t)b * SEQ + t) * INSZ + k];
}

// ---------------- prologue 2: Wih -> lane-matched layout -------------------
// float2 entry e: jt = e>>14; kk4 = (e>>7)&127; lane = (e>>2)&31; ki = e&3.
// k = kk4*4+ki; jl = lane>>1; gp = lane&1; j = jt*16+jl.
__global__ void wtrans_wih(const float* __restrict__ Wih) {
    int e = blockIdx.x * blockDim.x + threadIdx.x;   // 0..524287
    int jt   = e >> 14;
    int kk4  = (e >> 7) & 127;
    int lane = (e >> 2) & 31;
    int ki   = e & 3;
    int k = kk4 * 4 + ki;
    int jl = lane >> 1, gp = lane & 1;
    int j = jt * 16 + jl;
    float a = Wih[(size_t)k * G4 + j + (gp ? 2 * HSZ : 0)];
    float b = Wih[(size_t)k * G4 + j + (gp ? 3 * HSZ : HSZ)];
    ((float2*)g_wihT)[e] = make_float2(a, b);
}

// ---------------- fused persistent LSTM ------------------------------------
// 128 CTAs (1/SM). gates = [h_t; x_t] @ [W_hh; W_ih] + bias as ONE K=1024 gemm:
// the x-half (no serial dependency) runs between barrier-arrive and barrier-
// wait, filling the sync bubble. sT smem buffer is time-shared (x then h).
__global__ __launch_bounds__(256, 1) void lstm_persist(
    const float* __restrict__ Whh, const float* __restrict__ bias,
    const float* __restrict__ h0,  const float* __restrict__ c0,
    float* __restrict__ out) {
    extern __shared__ float smem[];
    float2* W2 = (float2*)smem;           // W_hh slice [k][lane] 128KB
    float*  sT = smem + 32768;            // [k][b] (x then h)     32KB
    float*  red = smem + 32768 + 8192;    // [warp][gate][b][jl]   32KB

    const int tid  = threadIdx.x;
    const int wid  = tid >> 5;
    const int lane = tid & 31;
    const int jt = blockIdx.x & 31, bt = blockIdx.x >> 5;
    const int j0 = jt * 16, b0 = bt * 16;
    unsigned* cnt = &g_cnt4[bt][0];

    const int bl = tid >> 4, jl_u = tid & 15;
    const int b = b0 + bl, j = j0 + jl_u;

    // init h state slice
    __stcg(&g_hT[0][j * BATCH + b], h0[(size_t)b * HSZ + j]);

    // load W_hh slice once: 512 k x 16 jl x 4 gates = 128KB
    for (int idx = tid; idx < 512 * 16; idx += 256) {
        int k = idx >> 4, jl = idx & 15;
        const float* wr = Whh + (size_t)k * G4 + j0 + jl;
        W2[k * 32 + jl * 2 + 0] = make_float2(wr[0],       wr[HSZ]);
        W2[k * 32 + jl * 2 + 1] = make_float2(wr[2 * HSZ], wr[3 * HSZ]);
    }

    float cc = c0[(size_t)b * HSZ + j];
    const float bi = bias[j], bf = bias[j + HSZ];
    const float bg = bias[j + 2 * HSZ], bo = bias[j + 3 * HSZ];

    const int ks0 = wid * 64;
    const int jl_c = lane >> 1, gp = lane & 1;
    float* rA = &red[((wid * 4 + gp * 2 + 0) * 16) * 16 + jl_c];
    float* rB = &red[((wid * 4 + gp * 2 + 1) * 16) * 16 + jl_c];

    // per-warp W_ih stream base (float4 view of lane-matched layout)
    const float4* wg4 = ((const float4*)g_wihT) + (size_t)jt * 8192 + lane * 2;

    // --- prologue barrier; tid0 keeps epoch base B in a register -----------
    __syncthreads();
    unsigned B = 0;
    if (tid == 0) {
        __threadfence();
        unsigned tk = atomicAdd(cnt, 1u) + 1u;
        B = (tk + (GRP - 1)) & ~(unsigned)(GRP - 1);
        while (*((volatile unsigned*)cnt) < B) { }
        __threadfence();
    }
    __syncthreads();

    for (int t = 0; t < SEQ; t++) {
        const int cur = t & 1;

        // ---- stage x_t into sT (from transposed g_xT, coalesced) ----
        {
            const float* xrow = g_xT + (size_t)t * (INSZ * BATCH);
#pragma unroll
            for (int it = 0; it < 8; it++) {
                int lin = tid + it * 256;
                int k = lin >> 2, b4 = (lin & 3) << 2;
                float4 v = __ldg((const float4*)&xrow[k * BATCH + b0 + b4]);
                *(float4*)&sT[k * 16 + b4] = v;
            }
        }
        __syncthreads();

        // ---- x-half gemm (no dependency: fills barrier-wait bubble) ----
        unsigned long long accA[8], accB[8];
#pragma unroll
        for (int p = 0; p < 8; p++) { accA[p] = 0ull; accB[p] = 0ull; }

#pragma unroll 4
        for (int c = 0; c < 16; c++) {
            const float4* wp = wg4 + (size_t)((ks0 >> 2) + c) * 64;
            float4 w01 = __ldg(wp);
            float4 w23 = __ldg(wp + 1);
            int kb = ks0 + c * 4;
            gemm_k(sT, kb + 0, w01.x, w01.y, accA, accB);
            gemm_k(sT, kb + 1, w01.z, w01.w, accA, accB);
            gemm_k(sT, kb + 2, w23.x, w23.y, accA, accB);
            gemm_k(sT, kb + 3, w23.z, w23.w, accA, accB);
        }

        // ---- wait: all group CTAs have stored h_t (arrives of iter t-1) ----
        if (tid == 0) {
            unsigned target = B + 32u * (unsigned)t;
            while (*((volatile unsigned*)cnt) < target) { }
            __threadfence();
        }
        __syncthreads();

        // ---- stage h_t into sT (overwrite; all warps past x-gemm) ----
        {
            const float* hin = g_hT[cur];
#pragma unroll
            for (int it = 0; it < 8; it++) {
                int lin = tid + it * 256;
                int k = lin >> 2, b4 = (lin & 3) << 2;
                float4 v = __ldcg((const float4*)&hin[k * BATCH + b0 + b4]);
                *(float4*)&sT[k * 16 + b4] = v;
            }
        }
        __syncthreads();

        // ---- h-half gemm (accumulates into same registers) ----
#pragma unroll 4
        for (int k = ks0; k < ks0 + 64; k++) {
            float2 w = W2[k * 32 + lane];
            gemm_k(sT, k, w.x, w.y, accA, accB);
        }

        // ---- write split-K partials ----
#pragma unroll
        for (int p = 0; p < 8; p++) {
            float lo, hi;
            unpack2(accA[p], lo, hi);
            rA[(2 * p) * 16] = lo; rA[(2 * p + 1) * 16] = hi;
            unpack2(accB[p], lo, hi);
            rB[(2 * p) * 16] = lo; rB[(2 * p + 1) * 16] = hi;
        }
        __syncthreads();

        // ---- reduce 8 warps + pointwise LSTM cell ----
        float si = 0.f, sf = 0.f, sg = 0.f, so = 0.f;
#pragma unroll
        for (int w = 0; w < 8; w++) {
            const float* rp = &red[((w * 4) * 16 + bl) * 16 + jl_u];
            si += rp[0];
            sf += rp[256];
            sg += rp[512];
            so += rp[768];
        }
        float gi = si + bi, gf = sf + bf, gg = sg + bg, go = so + bo;
        float iv = fast_sigmoid(gi), fv = fast_sigmoid(gf);
        float gv = fast_tanh(gg),    ov = fast_sigmoid(go);
        cc = fv * cc + iv * gv;
        float hv = ov * fast_tanh(cc);

        __stcg(&g_hT[cur ^ 1][j * BATCH + b], hv);
        out[((size_t)b * SEQ + t) * HSZ + j] = hv;
        if (t == SEQ - 1) {
            out[(size_t)BATCH * SEQ * HSZ + (size_t)b * HSZ + j] = hv;
            out[(size_t)BATCH * SEQ * HSZ + BATCH * HSZ + (size_t)b * HSZ + j] = cc;
        }

        // ---- arrive (wait deferred to next iteration, after x-gemm) ----
        __syncthreads();
        if (tid == 0) {
            __threadfence();
            atomicAdd(cnt, 1u);
        }
    }
}

// ---------------- launch ----------------------------------------------------
extern "C" void kernel_launch(void* const* d_in, const int* in_sizes, int n_in,
                              void* d_out, int out_size) {
    const float* x    = (const float*)d_in[0];
    const float* wih  = (const float*)d_in[1];
    const float* whh  = (const float*)d_in[2];
    const float* bias = (const float*)d_in[3];
    const float* h0   = (const float*)d_in[4];
    const float* c0   = (const float*)d_in[5];
    float* out = (float*)d_out;

    const int smem_bytes = 131072 + 32768 + 32768;   // 192KB
    cudaFuncSetAttribute(lstm_persist, cudaFuncAttributeMaxDynamicSharedMemorySize,
                         smem_bytes);

    wtrans_x<<<65536, 256>>>(x);
    wtrans_wih<<<2048, 256>>>(wih);
    lstm_persist<<<NCTA, 256, smem_bytes>>>(whh, bias, h0, c0, out);
}

// round 10
// speedup vs baseline: 1.0743x; 1.0743x over previous
#include <cuda_runtime.h>
#include <cstdint>
#include <math.h>

#define BATCH 64
#define SEQ   512
#define INSZ  512
#define HSZ   512
#define G4    2048   // 4*HSZ
#define NCTA  128
#define GRP   32     // CTAs per bt-group barrier

// ---------------- scratch (device globals; no allocation allowed) ----------
__device__ float g_xproj[(size_t)BATCH * SEQ * G4];   // x @ W_ih, row = b*SEQ+t
__device__ float g_hT[2][HSZ * BATCH];                // transposed hidden state: [j][b]
__device__ unsigned g_cnt4[4][32];                    // 4 group counters, 128B apart

// ---------------- f32x2 packed math helpers (sm_103a) ----------------------
__device__ __forceinline__ unsigned long long pack2(float lo, float hi) {
    unsigned long long r;
    asm("mov.b64 %0, {%1, %2};" : "=l"(r) : "f"(lo), "f"(hi));
    return r;
}
__device__ __forceinline__ void unpack2(unsigned long long v, float& lo, float& hi) {
    asm("mov.b64 {%0, %1}, %2;" : "=f"(lo), "=f"(hi) : "l"(v));
}
__device__ __forceinline__ unsigned long long ffma2(unsigned long long a,
                                                    unsigned long long b,
                                                    unsigned long long c) {
    unsigned long long d;
    asm("fma.rn.f32x2 %0, %1, %2, %3;" : "=l"(d) : "l"(a), "l"(b), "l"(c));
    return d;
}

// ---------------- fast activations (MUFU-based, rel err ~1e-6) -------------
__device__ __forceinline__ float ex2f(float x) {
    float y; asm("ex2.approx.f32 %0, %1;" : "=f"(y) : "f"(x)); return y;
}
__device__ __forceinline__ float rcpf(float x) {
    float y; asm("rcp.approx.f32 %0, %1;" : "=f"(y) : "f"(x)); return y;
}
#define LOG2E 1.4426950408889634f
__device__ __forceinline__ float fast_sigmoid(float x) {
    return rcpf(1.0f + ex2f(-x * LOG2E));
}
__device__ __forceinline__ float fast_tanh(float x) {
    float a = fabsf(x);
    float t = ex2f(-2.0f * LOG2E * a);
    float r = 1.0f - 2.0f * t * rcpf(1.0f + t);
    return copysignf(r, x);
}

// ---------------- kernel 1: x_proj = x @ W_ih (v3: double-buffered) --------
// CTA tile 128(M) x 128(N), BK=16, 256 threads. Thread tile 8m x 8n, M-pair
// FFMA2 accumulators. Ping-pong As/Bd staging: next tile's LDGs issue before
// computing the current tile, hiding L2/DRAM latency under 512 FFMA2.
__global__ __launch_bounds__(256) void xproj_gemm(const float* __restrict__ X,
                                                  const float* __restrict__ Wih) {
    __shared__ float  As[2][16][128];     // [buf][k][m]          16KB
    __shared__ float2 Bd[2][16][8][16];   // [buf][k][n][tx] dup  32KB

    const int tid = threadIdx.x;
    const int m0 = blockIdx.y * 128;
    const int n0 = blockIdx.x * 128;
    const int tx = tid & 15;           // n: 8 cols at n0 + tx*8
    const int ty = tid >> 4;           // m: 8 rows at m0 + ty*8

    // staging identities
    const int arow = tid >> 1;           // 0..127
    const int akq  = (tid & 1) * 8;      // 0 or 8
    const int brow = tid >> 4;           // 0..15 (k within block)
    const int bcg  = tid & 15;           // n-octet owner

    const float* aptr = &X[(size_t)(m0 + arow) * INSZ + akq];
    const float* bptr = &Wih[(size_t)brow * G4 + n0 + bcg * 8];

    unsigned long long acc[4][8];
#pragma unroll
    for (int p = 0; p < 4; p++)
#pragma unroll
        for (int n = 0; n < 8; n++) acc[p][n] = 0ull;

    // prologue: stage tile k0=0 into buf 0
    {
        float4 a0 = *(const float4*)(aptr);
        float4 a1 = *(const float4*)(aptr + 4);
        float4 bv0 = *(const float4*)(bptr);
        float4 bv1 = *(const float4*)(bptr + 4);
        As[0][akq + 0][arow] = a0.x;  As[0][akq + 1][arow] = a0.y;
        As[0][akq + 2][arow] = a0.z;  As[0][akq + 3][arow] = a0.w;
        As[0][akq + 4][arow] = a1.x;  As[0][akq + 5][arow] = a1.y;
        As[0][akq + 6][arow] = a1.z;  As[0][akq + 7][arow] = a1.w;
        Bd[0][brow][0][bcg] = make_float2(bv0.x, bv0.x);
        Bd[0][brow][1][bcg] = make_float2(bv0.y, bv0.y);
        Bd[0][brow][2][bcg] = make_float2(bv0.z, bv0.z);
        Bd[0][brow][3][bcg] = make_float2(bv0.w, bv0.w);
        Bd[0][brow][4][bcg] = make_float2(bv1.x, bv1.x);
        Bd[0][brow][5][bcg] = make_float2(bv1.y, bv1.y);
        Bd[0][brow][6][bcg] = make_float2(bv1.z, bv1.z);
        Bd[0][brow][7][bcg] = make_float2(bv1.w, bv1.w);
    }

    int buf = 0;
    for (int k0 = 0; k0 < INSZ; k0 += 16) {
        __syncthreads();

        // prefetch next tile into registers (LDG latency hides under compute)
        const bool has = (k0 + 16 < INSZ);
        float4 na0, na1, nb0, nb1;
        if (has) {
            na0 = *(const float4*)(aptr + (k0 + 16));
            na1 = *(const float4*)(aptr + (k0 + 16) + 4);
            nb0 = *(const float4*)(bptr + (size_t)(k0 + 16) * G4);
            nb1 = *(const float4*)(bptr + (size_t)(k0 + 16) * G4 + 4);
        }

        // compute current tile
#pragma unroll
        for (int kk = 0; kk < 16; kk++) {
            ulonglong2 a01 = *(const ulonglong2*)&As[buf][kk][ty * 8];
            ulonglong2 a23 = *(const ulonglong2*)&As[buf][kk][ty * 8 + 4];
#pragma unroll
            for (int n = 0; n < 8; n++) {
                unsigned long long bb = *(const unsigned long long*)&Bd[buf][kk][n][tx];
                acc[0][n] = ffma2(a01.x, bb, acc[0][n]);
                acc[1][n] = ffma2(a01.y, bb, acc[1][n]);
                acc[2][n] = ffma2(a23.x, bb, acc[2][n]);
                acc[3][n] = ffma2(a23.y, bb, acc[3][n]);
            }
        }

        // store next tile into the idle buffer
        if (has) {
            const int nb = buf ^ 1;
            As[nb][akq + 0][arow] = na0.x;  As[nb][akq + 1][arow] = na0.y;
            As[nb][akq + 2][arow] = na0.z;  As[nb][akq + 3][arow] = na0.w;
            As[nb][akq + 4][arow] = na1.x;  As[nb][akq + 5][arow] = na1.y;
            As[nb][akq + 6][arow] = na1.z;  As[nb][akq + 7][arow] = na1.w;
            Bd[nb][brow][0][bcg] = make_float2(nb0.x, nb0.x);
            Bd[nb][brow][1][bcg] = make_float2(nb0.y, nb0.y);
            Bd[nb][brow][2][bcg] = make_float2(nb0.z, nb0.z);
            Bd[nb][brow][3][bcg] = make_float2(nb0.w, nb0.w);
            Bd[nb][brow][4][bcg] = make_float2(nb1.x, nb1.x);
            Bd[nb][brow][5][bcg] = make_float2(nb1.y, nb1.y);
            Bd[nb][brow][6][bcg] = make_float2(nb1.z, nb1.z);
            Bd[nb][brow][7][bcg] = make_float2(nb1.w, nb1.w);
        }
        buf ^= 1;
    }

    // epilogue: acc[p][n] = rows (m0+ty*8+2p, +1), col n0+tx*8+n
#pragma unroll
    for (int p = 0; p < 4; p++) {
        float lo[8], hi[8];
#pragma unroll
        for (int n = 0; n < 8; n++) unpack2(acc[p][n], lo[n], hi[n]);
        float* r0 = &g_xproj[(size_t)(m0 + ty * 8 + 2 * p) * G4 + n0 + tx * 8];
        float* r1 = r0 + G4;
        *(float4*)(r0)     = make_float4(lo[0], lo[1], lo[2], lo[3]);
        *(float4*)(r0 + 4) = make_float4(lo[4], lo[5], lo[6], lo[7]);
        *(float4*)(r1)     = make_float4(hi[0], hi[1], hi[2], hi[3]);
        *(float4*)(r1 + 4) = make_float4(hi[4], hi[5], hi[6], hi[7]);
    }
}

// ---------------- kernel 2: persistent LSTM recurrence (R8 proven) ---------
__global__ __launch_bounds__(256, 1) void lstm_persist(
    const float* __restrict__ Whh, const float* __restrict__ bias,
    const float* __restrict__ h0,  const float* __restrict__ c0,
    float* __restrict__ out) {
    extern __shared__ float smem[];
    float2* W2  = (float2*)smem;          // [k][jl*2+gp] 128KB
    float*  hsT = smem + 32768;           // [k][b]        32KB
    float*  red = smem + 32768 + 8192;    // [warp][gate][b][jl] 32KB

    const int tid  = threadIdx.x;
    const int wid  = tid >> 5;
    const int lane = tid & 31;
    const int jt = blockIdx.x & 31, bt = blockIdx.x >> 5;
    const int j0 = jt * 16, b0 = bt * 16;
    unsigned* cnt = &g_cnt4[bt][0];

    const int bl = tid >> 4, jl_u = tid & 15;
    const int b = b0 + bl, j = j0 + jl_u;

    // init h state slice
    __stcg(&g_hT[0][j * BATCH + b], h0[(size_t)b * HSZ + j]);

    // load W slice once: 512 k x 16 jl x 4 gates = 128KB
    for (int idx = tid; idx < 512 * 16; idx += 256) {
        int k = idx >> 4, jl = idx & 15;
        const float* wr = Whh + (size_t)k * G4 + j0 + jl;
        W2[k * 32 + jl * 2 + 0] = make_float2(wr[0],       wr[HSZ]);
        W2[k * 32 + jl * 2 + 1] = make_float2(wr[2 * HSZ], wr[3 * HSZ]);
    }

    float cc = c0[(size_t)b * HSZ + j];
    const float bi = bias[j], bf = bias[j + HSZ];
    const float bg = bias[j + 2 * HSZ], bo = bias[j + 3 * HSZ];

    const int ks0 = wid * 64;
    const int jl_c = lane >> 1, gp = lane & 1;
    float* rA = &red[((wid * 4 + gp * 2 + 0) * 16) * 16 + jl_c];
    float* rB = &red[((wid * 4 + gp * 2 + 1) * 16) * 16 + jl_c];

    // group barrier after init writes (monotonic counter: replay-safe)
    __syncthreads();
    if (tid == 0) {
        __threadfence();
        unsigned tk = atomicAdd(cnt, 1u) + 1u;
        unsigned target = (tk + (GRP - 1)) & ~(unsigned)(GRP - 1);
        while (*((volatile unsigned*)cnt) < target) { }
        __threadfence();
    }
    __syncthreads();

    for (int t = 0; t < SEQ; t++) {
        const int cur = t & 1;
        const float* hin = g_hT[cur];

        // prefetch this step's x_proj contribution (consumed post-gemm)
        const float* xp = g_xproj + ((size_t)b * SEQ + t) * G4 + j;
        float xi = __ldg(xp);
        float xf = __ldg(xp + HSZ);
        float xg = __ldg(xp + 2 * HSZ);
        float xo = __ldg(xp + 3 * HSZ);

        // stage h tile: [k][b] transposed layout, conflict-free, L2-coherent
#pragma unroll
        for (int it = 0; it < 8; it++) {
            int lin = tid + it * 256;            // float4 slot 0..2047
            int k = lin >> 2, b4 = (lin & 3) << 2;
            float4 v = __ldcg((const float4*)&hin[k * BATCH + b0 + b4]);
            *(float4*)&hsT[k * 16 + b4] = v;
        }
        __syncthreads();

        // GEMM slice: 16 f32x2 accumulators packed over batch pairs
        unsigned long long accA[8], accB[8];
#pragma unroll
        for (int p = 0; p < 8; p++) { accA[p] = 0ull; accB[p] = 0ull; }

#pragma unroll 4
        for (int k = ks0; k < ks0 + 64; k++) {
            float2 w = W2[k * 32 + lane];
            unsigned long long wa = pack2(w.x, w.x);
            unsigned long long wb = pack2(w.y, w.y);
            const ulonglong2* hp = (const ulonglong2*)&hsT[k * 16];
            ulonglong2 h01 = hp[0], h23 = hp[1], h45 = hp[2], h67 = hp[3];
            accA[0] = ffma2(h01.x, wa, accA[0]); accB[0] = ffma2(h01.x, wb, accB[0]);
            accA[1] = ffma2(h01.y, wa, accA[1]); accB[1] = ffma2(h01.y, wb, accB[1]);
            accA[2] = ffma2(h23.x, wa, accA[2]); accB[2] = ffma2(h23.x, wb, accB[2]);
            accA[3] = ffma2(h23.y, wa, accA[3]); accB[3] = ffma2(h23.y, wb, accB[3]);
            accA[4] = ffma2(h45.x, wa, accA[4]); accB[4] = ffma2(h45.x, wb, accB[4]);
            accA[5] = ffma2(h45.y, wa, accA[5]); accB[5] = ffma2(h45.y, wb, accB[5]);
            accA[6] = ffma2(h67.x, wa, accA[6]); accB[6] = ffma2(h67.x, wb, accB[6]);
            accA[7] = ffma2(h67.y, wa, accA[7]); accB[7] = ffma2(h67.y, wb, accB[7]);
        }

        // write split-K partials
#pragma unroll
        for (int p = 0; p < 8; p++) {
            float lo, hi;
            unpack2(accA[p], lo, hi);
            rA[(2 * p) * 16] = lo; rA[(2 * p + 1) * 16] = hi;
            unpack2(accB[p], lo, hi);
            rB[(2 * p) * 16] = lo; rB[(2 * p + 1) * 16] = hi;
        }
        __syncthreads();

        // reduce 8 warps + pointwise LSTM cell (fast activations)
        float si = 0.f, sf = 0.f, sg = 0.f, so = 0.f;
#pragma unroll
        for (int w = 0; w < 8; w++) {
            const float* rp = &red[((w * 4) * 16 + bl) * 16 + jl_u];
            si += rp[0];
            sf += rp[256];
            sg += rp[512];
            so += rp[768];
        }
        float gi = si + xi + bi, gf = sf + xf + bf;
        float gg = sg + xg + bg, go = so + xo + bo;
        float iv = fast_sigmoid(gi), fv = fast_sigmoid(gf);
        float gv = fast_tanh(gg),    ov = fast_sigmoid(go);
        cc = fv * cc + iv * gv;
        float hv = ov * fast_tanh(cc);

        // cross-CTA-visible h store first, then output
        __stcg(&g_hT[cur ^ 1][j * BATCH + b], hv);
        out[((size_t)b * SEQ + t) * HSZ + j] = hv;
        if (t == SEQ - 1) {
            out[(size_t)BATCH * SEQ * HSZ + (size_t)b * HSZ + j] = hv;
            out[(size_t)BATCH * SEQ * HSZ + BATCH * HSZ + (size_t)b * HSZ + j] = cc;
        }

        // per-bt-group barrier (32 arrivals, monotonic: replay-safe)
        __syncthreads();
        if (tid == 0) {
            __threadfence();
            unsigned tk = atomicAdd(cnt, 1u) + 1u;
            unsigned target = (tk + (GRP - 1)) & ~(unsigned)(GRP - 1);
            while (*((volatile unsigned*)cnt) < target) { }
            __threadfence();
        }
        __syncthreads();
    }
}

// ---------------- launch ----------------------------------------------------
extern "C" void kernel_launch(void* const* d_in, const int* in_sizes, int n_in,
                              void* d_out, int out_size) {
    const float* x    = (const float*)d_in[0];
    const float* wih  = (const float*)d_in[1];
    const float* whh  = (const float*)d_in[2];
    const float* bias = (const float*)d_in[3];
    const float* h0   = (const float*)d_in[4];
    const float* c0   = (const float*)d_in[5];
    float* out = (float*)d_out;

    const int smem_bytes = 131072 + 32768 + 32768;   // 192KB
    cudaFuncSetAttribute(lstm_persist, cudaFuncAttributeMaxDynamicSharedMemorySize,
                         smem_bytes);

    // 128x128 tiles: grid = (2048/128, 32768/128) = (16, 256)
    xproj_gemm<<<dim3(16, 256), 256>>>(x, wih);
    lstm_persist<<<NCTA, 256, smem_bytes>>>(whh, bias, h0, c0, out);
}

// round 12
// speedup vs baseline: 1.3594x; 1.2654x over previous
#include <cuda_runtime.h>
#include <cuda_bf16.h>
#include <cstdint>
#include <math.h>

#define BATCH 64
#define SEQ   512
#define INSZ  512
#define HSZ   512
#define G4    2048   // 4*HSZ
#define NCTA  128
#define GRP   32     // CTAs per bt-group barrier

// ---------------- scratch (device globals; no allocation allowed) ----------
__device__ float g_xproj[(size_t)BATCH * SEQ * G4];      // x @ W_ih fp32
__device__ float g_hT[2][HSZ * BATCH];                   // transposed hidden [j][b]
__device__ unsigned g_cnt4[4][32];                       // group counters
__device__ __nv_bfloat16 g_xh[(size_t)BATCH * SEQ * INSZ];   // 32MB x hi
__device__ __nv_bfloat16 g_xl[(size_t)BATCH * SEQ * INSZ];   // 32MB x lo
__device__ __nv_bfloat16 g_wth[(size_t)G4 * INSZ];           // 2MB  W_ih^T hi [n][k]
__device__ __nv_bfloat16 g_wtl[(size_t)G4 * INSZ];           // 2MB  W_ih^T lo

// ---------------- f32x2 packed math helpers (sm_103a) ----------------------
__device__ __forceinline__ unsigned long long pack2(float lo, float hi) {
    unsigned long long r;
    asm("mov.b64 %0, {%1, %2};" : "=l"(r) : "f"(lo), "f"(hi));
    return r;
}
__device__ __forceinline__ void unpack2(unsigned long long v, float& lo, float& hi) {
    asm("mov.b64 {%0, %1}, %2;" : "=f"(lo), "=f"(hi) : "l"(v));
}
__device__ __forceinline__ unsigned long long ffma2(unsigned long long a,
                                                    unsigned long long b,
                                                    unsigned long long c) {
    unsigned long long d;
    asm("fma.rn.f32x2 %0, %1, %2, %3;" : "=l"(d) : "l"(a), "l"(b), "l"(c));
    return d;
}

// ---------------- fast activations -----------------------------------------
__device__ __forceinline__ float ex2f(float x) {
    float y; asm("ex2.approx.f32 %0, %1;" : "=f"(y) : "f"(x)); return y;
}
__device__ __forceinline__ float rcpf(float x) {
    float y; asm("rcp.approx.f32 %0, %1;" : "=f"(y) : "f"(x)); return y;
}
#define LOG2E 1.4426950408889634f
__device__ __forceinline__ float fast_sigmoid(float x) {
    return rcpf(1.0f + ex2f(-x * LOG2E));
}
__device__ __forceinline__ float fast_tanh(float x) {
    float a = fabsf(x);
    float t = ex2f(-2.0f * LOG2E * a);
    float r = 1.0f - 2.0f * t * rcpf(1.0f + t);
    return copysignf(r, x);
}

// ---------------- mma.sync / ldmatrix / cp.async helpers (plain sm_103) ----
__device__ __forceinline__ uint32_t smem_u32(const void* p) {
    uint32_t a;
    asm("{ .reg .u64 t; cvta.to.shared.u64 t, %1; cvt.u32.u64 %0, t; }"
        : "=r"(a) : "l"(p));
    return a;
}
__device__ __forceinline__ void ldsm4(uint32_t addr, uint32_t r[4]) {
    asm volatile("ldmatrix.sync.aligned.m8n8.x4.shared.b16 {%0,%1,%2,%3}, [%4];"
                 : "=r"(r[0]), "=r"(r[1]), "=r"(r[2]), "=r"(r[3]) : "r"(addr));
}
__device__ __forceinline__ void mma16816(float c[4], const uint32_t a[4],
                                         uint32_t b0, uint32_t b1) {
    asm volatile(
        "mma.sync.aligned.m16n8k16.row.col.f32.bf16.bf16.f32 "
        "{%0,%1,%2,%3}, {%4,%5,%6,%7}, {%8,%9}, {%0,%1,%2,%3};"
        : "+f"(c[0]), "+f"(c[1]), "+f"(c[2]), "+f"(c[3])
        : "r"(a[0]), "r"(a[1]), "r"(a[2]), "r"(a[3]), "r"(b0), "r"(b1));
}
#define CP16(s, g) asm volatile("cp.async.cg.shared.global [%0], [%1], 16;" :: "r"(s), "l"(g))
#define CPCOMMIT() asm volatile("cp.async.commit_group;" ::: "memory")
#define CPWAIT(n)  asm volatile("cp.async.wait_group %0;" :: "n"(n) : "memory")

// ---------------- prologue: bf16 hi/lo conversions -------------------------
__global__ void conv_x(const float* __restrict__ X) {
    size_t i = (size_t)blockIdx.x * blockDim.x + threadIdx.x;
    float v = X[i];
    __nv_bfloat16 h = __float2bfloat16(v);
    g_xh[i] = h;
    g_xl[i] = __float2bfloat16(v - __bfloat162float(h));
}
__global__ void conv_w(const float* __restrict__ Wih) {
    int idx = blockIdx.x * blockDim.x + threadIdx.x;  // k*2048+n (coalesced read)
    int k = idx >> 11, n = idx & 2047;
    float v = Wih[idx];
    __nv_bfloat16 h = __float2bfloat16(v);
    g_wth[(size_t)n * INSZ + k] = h;
    g_wtl[(size_t)n * INSZ + k] = __float2bfloat16(v - __bfloat162float(h));
}

// ---------------- kernel 1: x_proj via mma.sync bf16-split -----------------
// CTA 128(M) x 128(N), 8 warps (warp tile 32m x 64n), BK=64, cp.async
// double-buffered. Rows padded to 144B: ldmatrix conflict-free.
#define ROWB   144            // 64 bf16 data + 8 pad = 72 bf16 = 144B
#define TILEB  (128 * ROWB)   // 18432B per 128x64 tile
#define BUFB   (4 * TILEB)    // Ah, Al, Bh, Bl = 73728B
#define XSMEM  (2 * BUFB)     // 147456B

__device__ __forceinline__ void stage_chunk(uint32_t sb, int buf, int ch,
                                            int m0, int n0, int tid) {
    const __nv_bfloat16* srcs[4] = {g_xh, g_xl, g_wth, g_wtl};
    const int row0s[4] = {m0, m0, n0, n0};
#pragma unroll
    for (int tile = 0; tile < 4; tile++) {
        const __nv_bfloat16* src = srcs[tile];
        const int row0 = row0s[tile];
        uint32_t sbase = sb + buf * BUFB + tile * TILEB;
#pragma unroll
        for (int s = 0; s < 4; s++) {
            int slot = tid + s * 256;         // 0..1023
            int row = slot >> 3, c = slot & 7;
            const char* g = (const char*)(src + (size_t)(row0 + row) * INSZ + ch * 64) + c * 16;
            CP16(sbase + row * ROWB + c * 16, g);
        }
    }
    CPCOMMIT();
}

__global__ __launch_bounds__(256, 1) void xproj_mma() {
    extern __shared__ char sm[];
    const uint32_t sb = smem_u32(sm);
    const int tid = threadIdx.x;
    const int wid = tid >> 5;
    const int lane = tid & 31;
    const int m0 = blockIdx.y * 128;
    const int n0 = blockIdx.x * 128;
    const int wm = (wid & 3) * 32;   // warp m offset in tile
    const int wn = (wid >> 2) * 64;  // warp n offset in tile

    float acc[2][8][4];
#pragma unroll
    for (int mt = 0; mt < 2; mt++)
#pragma unroll
        for (int nt = 0; nt < 8; nt++)
#pragma unroll
            for (int q = 0; q < 4; q++) acc[mt][nt][q] = 0.0f;

    // ldmatrix lane-address components (byte offsets within a tile)
    const int arow_off = (wm + (lane & 15)) * ROWB + ((lane >> 4) * 8) * 2;
    const int brow_base = wn + (lane & 7) + ((lane >> 4) << 3);
    const int bk_off = (((lane >> 3) & 1) * 8) * 2;

    stage_chunk(sb, 0, 0, m0, n0, tid);

    for (int ch = 0; ch < 8; ch++) {
        const int buf = ch & 1;
        if (ch < 7) {
            stage_chunk(sb, buf ^ 1, ch + 1, m0, n0, tid);
            CPWAIT(1);
        } else {
            CPWAIT(0);
        }
        __syncthreads();

        const uint32_t Ah = sb + buf * BUFB;
        const uint32_t Al = Ah + TILEB;
        const uint32_t Bh = Al + TILEB;
        const uint32_t Bl = Bh + TILEB;

#pragma unroll
        for (int k16 = 0; k16 < 4; k16++) {
            const int kb = k16 * 32;   // 16 bf16 = 32 bytes
            uint32_t ah[2][4], al[2][4];
#pragma unroll
            for (int mt = 0; mt < 2; mt++) {
                ldsm4(Ah + arow_off + mt * 16 * ROWB + kb, ah[mt]);
                ldsm4(Al + arow_off + mt * 16 * ROWB + kb, al[mt]);
            }
            uint32_t bh[8][2], bl[8][2];
#pragma unroll
            for (int ng = 0; ng < 4; ng++) {
                uint32_t r[4];
                ldsm4(Bh + (brow_base + ng * 16) * ROWB + bk_off + kb, r);
                bh[ng * 2][0] = r[0]; bh[ng * 2][1] = r[1];
                bh[ng * 2 + 1][0] = r[2]; bh[ng * 2 + 1][1] = r[3];
                ldsm4(Bl + (brow_base + ng * 16) * ROWB + bk_off + kb, r);
                bl[ng * 2][0] = r[0]; bl[ng * 2][1] = r[1];
                bl[ng * 2 + 1][0] = r[2]; bl[ng * 2 + 1][1] = r[3];
            }
#pragma unroll
            for (int mt = 0; mt < 2; mt++)
#pragma unroll
                for (int nt = 0; nt < 8; nt++) {
                    mma16816(acc[mt][nt], ah[mt], bh[nt][0], bh[nt][1]);
                    mma16816(acc[mt][nt], ah[mt], bl[nt][0], bl[nt][1]);
                    mma16816(acc[mt][nt], al[mt], bh[nt][0], bh[nt][1]);
                }
        }
        __syncthreads();
    }

    // epilogue: c frag -> direct STG.64 (quad-contiguous)
#pragma unroll
    for (int mt = 0; mt < 2; mt++)
#pragma unroll
        for (int nt = 0; nt < 8; nt++) {
            int row = m0 + wm + mt * 16 + (lane >> 2);
            int col = n0 + wn + nt * 8 + (lane & 3) * 2;
            float* p0 = &g_xproj[(size_t)row * G4 + col];
            *(float2*)p0 = make_float2(acc[mt][nt][0], acc[mt][nt][1]);
            *(float2*)(p0 + (size_t)8 * G4) = make_float2(acc[mt][nt][2], acc[mt][nt][3]);
        }
}

// ---------------- kernel 2: persistent LSTM recurrence (R8/R10 proven) -----
__global__ __launch_bounds__(256, 1) void lstm_persist(
    const float* __restrict__ Whh, const float* __restrict__ bias,
    const float* __restrict__ h0,  const float* __restrict__ c0,
    float* __restrict__ out) {
    extern __shared__ float smem[];
    float2* W2  = (float2*)smem;          // [k][jl*2+gp] 128KB
    float*  hsT = smem + 32768;           // [k][b]        32KB
    float*  red = smem + 32768 + 8192;    // [warp][gate][b][jl] 32KB

    const int tid  = threadIdx.x;
    const int wid  = tid >> 5;
    const int lane = tid & 31;
    const int jt = blockIdx.x & 31, bt = blockIdx.x >> 5;
    const int j0 = jt * 16, b0 = bt * 16;
    unsigned* cnt = &g_cnt4[bt][0];

    const int bl = tid >> 4, jl_u = tid & 15;
    const int b = b0 + bl, j = j0 + jl_u;

    __stcg(&g_hT[0][j * BATCH + b], h0[(size_t)b * HSZ + j]);

    for (int idx = tid; idx < 512 * 16; idx += 256) {
        int k = idx >> 4, jl = idx & 15;
        const float* wr = Whh + (size_t)k * G4 + j0 + jl;
        W2[k * 32 + jl * 2 + 0] = make_float2(wr[0],       wr[HSZ]);
        W2[k * 32 + jl * 2 + 1] = make_float2(wr[2 * HSZ], wr[3 * HSZ]);
    }

    float cc = c0[(size_t)b * HSZ + j];
    const float bi = bias[j], bf = bias[j + HSZ];
    const float bg = bias[j + 2 * HSZ], bo = bias[j + 3 * HSZ];

    const int ks0 = wid * 64;
    const int jl_c = lane >> 1, gp = lane & 1;
    float* rA = &red[((wid * 4 + gp * 2 + 0) * 16) * 16 + jl_c];
    float* rB = &red[((wid * 4 + gp * 2 + 1) * 16) * 16 + jl_c];

    __syncthreads();
    if (tid == 0) {
        __threadfence();
        unsigned tk = atomicAdd(cnt, 1u) + 1u;
        unsigned target = (tk + (GRP - 1)) & ~(unsigned)(GRP - 1);
        while (*((volatile unsigned*)cnt) < target) { }
        __threadfence();
    }
    __syncthreads();

    for (int t = 0; t < SEQ; t++) {
        const int cur = t & 1;
        const float* hin = g_hT[cur];

        const float* xp = g_xproj + ((size_t)b * SEQ + t) * G4 + j;
        float xi = __ldg(xp);
        float xf = __ldg(xp + HSZ);
        float xg = __ldg(xp + 2 * HSZ);
        float xo = __ldg(xp + 3 * HSZ);

#pragma unroll
        for (int it = 0; it < 8; it++) {
            int lin = tid + it * 256;
            int k = lin >> 2, b4 = (lin & 3) << 2;
            float4 v = __ldcg((const float4*)&hin[k * BATCH + b0 + b4]);
            *(float4*)&hsT[k * 16 + b4] = v;
        }
        __syncthreads();

        unsigned long long accA[8], accB[8];
#pragma unroll
        for (int p = 0; p < 8; p++) { accA[p] = 0ull; accB[p] = 0ull; }

#pragma unroll 4
        for (int k = ks0; k < ks0 + 64; k++) {
            float2 w = W2[k * 32 + lane];
            unsigned long long wa = pack2(w.x, w.x);
            unsigned long long wb = pack2(w.y, w.y);
            const ulonglong2* hp = (const ulonglong2*)&hsT[k * 16];
            ulonglong2 h01 = hp[0], h23 = hp[1], h45 = hp[2], h67 = hp[3];
            accA[0] = ffma2(h01.x, wa, accA[0]); accB[0] = ffma2(h01.x, wb, accB[0]);
            accA[1] = ffma2(h01.y, wa, accA[1]); accB[1] = ffma2(h01.y, wb, accB[1]);
            accA[2] = ffma2(h23.x, wa, accA[2]); accB[2] = ffma2(h23.x, wb, accB[2]);
            accA[3] = ffma2(h23.y, wa, accA[3]); accB[3] = ffma2(h23.y, wb, accB[3]);
            accA[4] = ffma2(h45.x, wa, accA[4]); accB[4] = ffma2(h45.x, wb, accB[4]);
            accA[5] = ffma2(h45.y, wa, accA[5]); accB[5] = ffma2(h45.y, wb, accB[5]);
            accA[6] = ffma2(h67.x, wa, accA[6]); accB[6] = ffma2(h67.x, wb, accB[6]);
            accA[7] = ffma2(h67.y, wa, accA[7]); accB[7] = ffma2(h67.y, wb, accB[7]);
        }

#pragma unroll
        for (int p = 0; p < 8; p++) {
            float lo, hi;
            unpack2(accA[p], lo, hi);
            rA[(2 * p) * 16] = lo; rA[(2 * p + 1) * 16] = hi;
            unpack2(accB[p], lo, hi);
            rB[(2 * p) * 16] = lo; rB[(2 * p + 1) * 16] = hi;
        }
        __syncthreads();

        float si = 0.f, sf = 0.f, sg = 0.f, so = 0.f;
#pragma unroll
        for (int w = 0; w < 8; w++) {
            const float* rp = &red[((w * 4) * 16 + bl) * 16 + jl_u];
            si += rp[0];
            sf += rp[256];
            sg += rp[512];
            so += rp[768];
        }
        float gi = si + xi + bi, gf = sf + xf + bf;
        float gg = sg + xg + bg, go = so + xo + bo;
        float iv = fast_sigmoid(gi), fv = fast_sigmoid(gf);
        float gv = fast_tanh(gg),    ov = fast_sigmoid(go);
        cc = fv * cc + iv * gv;
        float hv = ov * fast_tanh(cc);

        __stcg(&g_hT[cur ^ 1][j * BATCH + b], hv);
        out[((size_t)b * SEQ + t) * HSZ + j] = hv;
        if (t == SEQ - 1) {
            out[(size_t)BATCH * SEQ * HSZ + (size_t)b * HSZ + j] = hv;
            out[(size_t)BATCH * SEQ * HSZ + BATCH * HSZ + (size_t)b * HSZ + j] = cc;
        }

        __syncthreads();
        if (tid == 0) {
            __threadfence();
            unsigned tk = atomicAdd(cnt, 1u) + 1u;
            unsigned target = (tk + (GRP - 1)) & ~(unsigned)(GRP - 1);
            while (*((volatile unsigned*)cnt) < target) { }
            __threadfence();
        }
        __syncthreads();
    }
}

// ---------------- launch ----------------------------------------------------
extern "C" void kernel_launch(void* const* d_in, const int* in_sizes, int n_in,
                              void* d_out, int out_size) {
    const float* x    = (const float*)d_in[0];
    const float* wih  = (const float*)d_in[1];
    const float* whh  = (const float*)d_in[2];
    const float* bias = (const float*)d_in[3];
    const float* h0   = (const float*)d_in[4];
    const float* c0   = (const float*)d_in[5];
    float* out = (float*)d_out;

    const int smem_bytes = 131072 + 32768 + 32768;   // 192KB (lstm)
    cudaFuncSetAttribute(lstm_persist, cudaFuncAttributeMaxDynamicSharedMemorySize,
                         smem_bytes);
    cudaFuncSetAttribute(xproj_mma, cudaFuncAttributeMaxDynamicSharedMemorySize,
                         XSMEM);

    conv_x<<<65536, 256>>>(x);
    conv_w<<<4096, 256>>>(wih);
    xproj_mma<<<dim3(16, 256), 256, XSMEM>>>();
    lstm_persist<<<NCTA, 256, smem_bytes>>>(whh, bias, h0, c0, out);
}

// round 13
// speedup vs baseline: 1.9487x; 1.4334x over previous
#include <cuda_runtime.h>
#include <cuda_bf16.h>
#include <cstdint>
#include <math.h>

#define BATCH 64
#define SEQ   512
#define INSZ  512
#define HSZ   512
#define G4    2048   // 4*HSZ
#define NCTA  128
#define GRP   32     // CTAs per bt-group barrier

// ---------------- scratch (device globals; no allocation allowed) ----------
__device__ float g_xproj[(size_t)BATCH * SEQ * G4];      // x @ W_ih fp32
__device__ unsigned g_cnt4[4][32];                       // group counters
__device__ __nv_bfloat16 g_xh[(size_t)BATCH * SEQ * INSZ];   // x hi
__device__ __nv_bfloat16 g_xl[(size_t)BATCH * SEQ * INSZ];   // x lo
__device__ __nv_bfloat16 g_wth[(size_t)G4 * INSZ];           // W_ih^T hi [n][k]
__device__ __nv_bfloat16 g_wtl[(size_t)G4 * INSZ];           // W_ih^T lo
__device__ __nv_bfloat16 g_whh_h[(size_t)G4 * HSZ];          // W_hh rearranged hi [cg][k]
__device__ __nv_bfloat16 g_whh_l[(size_t)G4 * HSZ];          // W_hh rearranged lo
__device__ __nv_bfloat16 g_hbh[2][BATCH * HSZ];              // h hi ping-pong [b][j]
__device__ __nv_bfloat16 g_hbl[2][BATCH * HSZ];              // h lo ping-pong [b][j]

// ---------------- fast activations -----------------------------------------
__device__ __forceinline__ float ex2f(float x) {
    float y; asm("ex2.approx.f32 %0, %1;" : "=f"(y) : "f"(x)); return y;
}
__device__ __forceinline__ float rcpf(float x) {
    float y; asm("rcp.approx.f32 %0, %1;" : "=f"(y) : "f"(x)); return y;
}
#define LOG2E 1.4426950408889634f
__device__ __forceinline__ float fast_sigmoid(float x) {
    return rcpf(1.0f + ex2f(-x * LOG2E));
}
__device__ __forceinline__ float fast_tanh(float x) {
    float a = fabsf(x);
    float t = ex2f(-2.0f * LOG2E * a);
    float r = 1.0f - 2.0f * t * rcpf(1.0f + t);
    return copysignf(r, x);
}

// ---------------- mma.sync / ldmatrix / cp.async helpers (plain sm_103) ----
__device__ __forceinline__ uint32_t smem_u32(const void* p) {
    uint32_t a;
    asm("{ .reg .u64 t; cvta.to.shared.u64 t, %1; cvt.u32.u64 %0, t; }"
        : "=r"(a) : "l"(p));
    return a;
}
__device__ __forceinline__ void ldsm4(uint32_t addr, uint32_t r[4]) {
    asm volatile("ldmatrix.sync.aligned.m8n8.x4.shared.b16 {%0,%1,%2,%3}, [%4];"
                 : "=r"(r[0]), "=r"(r[1]), "=r"(r[2]), "=r"(r[3]) : "r"(addr));
}
__device__ __forceinline__ void mma16816(float c[4], const uint32_t a[4],
                                         uint32_t b0, uint32_t b1) {
    asm volatile(
        "mma.sync.aligned.m16n8k16.row.col.f32.bf16.bf16.f32 "
        "{%0,%1,%2,%3}, {%4,%5,%6,%7}, {%8,%9}, {%0,%1,%2,%3};"
        : "+f"(c[0]), "+f"(c[1]), "+f"(c[2]), "+f"(c[3])
        : "r"(a[0]), "r"(a[1]), "r"(a[2]), "r"(a[3]), "r"(b0), "r"(b1));
}
#define CP16(s, g) asm volatile("cp.async.cg.shared.global [%0], [%1], 16;" :: "r"(s), "l"(g))
#define CPCOMMIT() asm volatile("cp.async.commit_group;" ::: "memory")
#define CPWAIT(n)  asm volatile("cp.async.wait_group %0;" :: "n"(n) : "memory")

__device__ __forceinline__ void st_bf16_cg(__nv_bfloat16* p, __nv_bfloat16 v) {
    unsigned short u = *reinterpret_cast<unsigned short*>(&v);
    asm volatile("st.global.cg.u16 [%0], %1;" :: "l"(p), "h"(u) : "memory");
}

// ---------------- prologue conversions -------------------------------------
__global__ void conv_x(const float* __restrict__ X) {
    size_t i = (size_t)blockIdx.x * blockDim.x + threadIdx.x;
    float v = X[i];
    __nv_bfloat16 h = __float2bfloat16(v);
    g_xh[i] = h;
    g_xl[i] = __float2bfloat16(v - __bfloat162float(h));
}
__global__ void conv_w(const float* __restrict__ Wih) {
    int idx = blockIdx.x * blockDim.x + threadIdx.x;
    int k = idx >> 11, n = idx & 2047;
    float v = Wih[idx];
    __nv_bfloat16 h = __float2bfloat16(v);
    g_wth[(size_t)n * INSZ + k] = h;
    g_wtl[(size_t)n * INSZ + k] = __float2bfloat16(v - __bfloat162float(h));
}
// W_hh rearranged per-CTA contiguous: cg = jt*64 + gate*16 + jl, layout [cg][k]
__global__ void conv_whh(const float* __restrict__ Whh) {
    int idx = blockIdx.x * blockDim.x + threadIdx.x;  // k*2048 + col (coalesced read)
    int k = idx >> 11, col = idx & 2047;
    int gate = col >> 9, rem = col & 511;
    int jt = rem >> 4, jl = rem & 15;
    size_t cg = (size_t)(jt * 64 + gate * 16 + jl);
    float v = Whh[idx];
    __nv_bfloat16 h = __float2bfloat16(v);
    g_whh_h[cg * HSZ + k] = h;
    g_whh_l[cg * HSZ + k] = __float2bfloat16(v - __bfloat162float(h));
}

// ---------------- kernel 1: x_proj via mma.sync bf16-split (R12 proven) ----
#define ROWB   144
#define TILEB  (128 * ROWB)
#define BUFB   (4 * TILEB)
#define XSMEM  (2 * BUFB)

__device__ __forceinline__ void stage_chunk(uint32_t sb, int buf, int ch,
                                            int m0, int n0, int tid) {
    const __nv_bfloat16* srcs[4] = {g_xh, g_xl, g_wth, g_wtl};
    const int row0s[4] = {m0, m0, n0, n0};
#pragma unroll
    for (int tile = 0; tile < 4; tile++) {
        const __nv_bfloat16* src = srcs[tile];
        const int row0 = row0s[tile];
        uint32_t sbase = sb + buf * BUFB + tile * TILEB;
#pragma unroll
        for (int s = 0; s < 4; s++) {
            int slot = tid + s * 256;
            int row = slot >> 3, c = slot & 7;
            const char* g = (const char*)(src + (size_t)(row0 + row) * INSZ + ch * 64) + c * 16;
            CP16(sbase + row * ROWB + c * 16, g);
        }
    }
    CPCOMMIT();
}

__global__ __launch_bounds__(256, 1) void xproj_mma() {
    extern __shared__ char sm[];
    const uint32_t sb = smem_u32(sm);
    const int tid = threadIdx.x;
    const int wid = tid >> 5;
    const int lane = tid & 31;
    const int m0 = blockIdx.y * 128;
    const int n0 = blockIdx.x * 128;
    const int wm = (wid & 3) * 32;
    const int wn = (wid >> 2) * 64;

    float acc[2][8][4];
#pragma unroll
    for (int mt = 0; mt < 2; mt++)
#pragma unroll
        for (int nt = 0; nt < 8; nt++)
#pragma unroll
            for (int q = 0; q < 4; q++) acc[mt][nt][q] = 0.0f;

    const int arow_off = (wm + (lane & 15)) * ROWB + ((lane >> 4) * 8) * 2;
    const int brow_base = wn + (lane & 7) + ((lane >> 4) << 3);
    const int bk_off = (((lane >> 3) & 1) * 8) * 2;

    stage_chunk(sb, 0, 0, m0, n0, tid);

    for (int ch = 0; ch < 8; ch++) {
        const int buf = ch & 1;
        if (ch < 7) {
            stage_chunk(sb, buf ^ 1, ch + 1, m0, n0, tid);
            CPWAIT(1);
        } else {
            CPWAIT(0);
        }
        __syncthreads();

        const uint32_t Ah = sb + buf * BUFB;
        const uint32_t Al = Ah + TILEB;
        const uint32_t Bh = Al + TILEB;
        const uint32_t Bl = Bh + TILEB;

#pragma unroll
        for (int k16 = 0; k16 < 4; k16++) {
            const int kb = k16 * 32;
            uint32_t ah[2][4], al[2][4];
#pragma unroll
            for (int mt = 0; mt < 2; mt++) {
                ldsm4(Ah + arow_off + mt * 16 * ROWB + kb, ah[mt]);
                ldsm4(Al + arow_off + mt * 16 * ROWB + kb, al[mt]);
            }
            uint32_t bh[8][2], bl[8][2];
#pragma unroll
            for (int ng = 0; ng < 4; ng++) {
                uint32_t r[4];
                ldsm4(Bh + (brow_base + ng * 16) * ROWB + bk_off + kb, r);
                bh[ng * 2][0] = r[0]; bh[ng * 2][1] = r[1];
                bh[ng * 2 + 1][0] = r[2]; bh[ng * 2 + 1][1] = r[3];
                ldsm4(Bl + (brow_base + ng * 16) * ROWB + bk_off + kb, r);
                bl[ng * 2][0] = r[0]; bl[ng * 2][1] = r[1];
                bl[ng * 2 + 1][0] = r[2]; bl[ng * 2 + 1][1] = r[3];
            }
#pragma unroll
            for (int mt = 0; mt < 2; mt++)
#pragma unroll
                for (int nt = 0; nt < 8; nt++) {
                    mma16816(acc[mt][nt], ah[mt], bh[nt][0], bh[nt][1]);
                    mma16816(acc[mt][nt], ah[mt], bl[nt][0], bl[nt][1]);
                    mma16816(acc[mt][nt], al[mt], bh[nt][0], bh[nt][1]);
                }
        }
        __syncthreads();
    }

#pragma unroll
    for (int mt = 0; mt < 2; mt++)
#pragma unroll
        for (int nt = 0; nt < 8; nt++) {
            int row = m0 + wm + mt * 16 + (lane >> 2);
            int col = n0 + wn + nt * 8 + (lane & 3) * 2;
            float* p0 = &g_xproj[(size_t)row * G4 + col];
            *(float2*)p0 = make_float2(acc[mt][nt][0], acc[mt][nt][1]);
            *(float2*)(p0 + (size_t)8 * G4) = make_float2(acc[mt][nt][2], acc[mt][nt][3]);
        }
}

// ---------------- kernel 2: persistent LSTM, mma.sync recurrence -----------
// smem rows padded to 1040B (65*16B: odd -> ldmatrix conflict-free).
// WH hi/lo resident (130KB), HS hi/lo per step (32.5KB), red 32KB.
#define WROWB 1040
#define OFF_WHH 0
#define OFF_WHL (OFF_WHH + 64 * WROWB)      // 66560
#define OFF_HSH (OFF_WHL + 64 * WROWB)      // 133120
#define OFF_HSL (OFF_HSH + 16 * WROWB)      // 149760
#define OFF_RED (OFF_HSL + 16 * WROWB)      // 166400
#define LSMEM   (OFF_RED + 32768)           // 199168

__global__ __launch_bounds__(256, 1) void lstm_persist(
    const float* __restrict__ bias, const float* __restrict__ h0,
    const float* __restrict__ c0,   float* __restrict__ out) {
    extern __shared__ char sm[];
    const uint32_t sb = smem_u32(sm);
    float* red = (float*)(sm + OFF_RED);

    const int tid  = threadIdx.x;
    const int wid  = tid >> 5;
    const int lane = tid & 31;
    const int jt = blockIdx.x & 31, bt = blockIdx.x >> 5;
    const int j0 = jt * 16, b0 = bt * 16;
    unsigned* cnt = &g_cnt4[bt][0];

    const int bl = tid >> 4, jl_u = tid & 15;
    const int b = b0 + bl, j = j0 + jl_u;

    // init h0 as bf16 hi/lo split
    {
        float hv = h0[(size_t)b * HSZ + j];
        __nv_bfloat16 hh = __float2bfloat16(hv);
        st_bf16_cg(&g_hbh[0][b * HSZ + j], hh);
        st_bf16_cg(&g_hbl[0][b * HSZ + j],
                   __float2bfloat16(hv - __bfloat162float(hh)));
    }

    // stage W_hh slice (64 rows x 512 k, hi+lo) into smem once
    for (int it = 0; it < 16; it++) {
        int slot = tid + it * 256;               // 0..4095
        int row = slot >> 6, c16 = slot & 63;
        size_t goff = ((size_t)(jt * 64 + row)) * HSZ + c16 * 8;
        *(uint4*)(sm + OFF_WHH + row * WROWB + c16 * 16) = *(const uint4*)(g_whh_h + goff);
        *(uint4*)(sm + OFF_WHL + row * WROWB + c16 * 16) = *(const uint4*)(g_whh_l + goff);
    }

    float cc = c0[(size_t)b * HSZ + j];
    const float bi = bias[j], bf = bias[j + HSZ];
    const float bg = bias[j + 2 * HSZ], bo = bias[j + 3 * HSZ];

    // mma identities: warp wid owns k-slice [wid*64, wid*64+64)
    const int kbase = wid * 128;                 // bytes (64 bf16)
    const int arow_off = (lane & 15) * WROWB + ((lane >> 4) * 8) * 2;
    const int brow_base = (lane & 7) + ((lane >> 4) << 3);
    const int bk_off = (((lane >> 3) & 1) * 8) * 2;

    // group barrier after init writes (monotonic counter: replay-safe)
    __syncthreads();
    if (tid == 0) {
        __threadfence();
        unsigned tk = atomicAdd(cnt, 1u) + 1u;
        unsigned target = (tk + (GRP - 1)) & ~(unsigned)(GRP - 1);
        while (*((volatile unsigned*)cnt) < target) { }
        __threadfence();
    }
    __syncthreads();

    for (int t = 0; t < SEQ; t++) {
        const int cur = t & 1;

        // prefetch x_proj contribution (consumed post-gemm)
        const float* xp = g_xproj + ((size_t)b * SEQ + t) * G4 + j;
        float xi = __ldg(xp);
        float xf = __ldg(xp + HSZ);
        float xg = __ldg(xp + 2 * HSZ);
        float xo = __ldg(xp + 3 * HSZ);

        // stage h (16 rows x 512 j, hi+lo) with .cg coherence
#pragma unroll
        for (int it = 0; it < 4; it++) {
            int slot = tid + it * 256;           // 0..1023
            int row = slot >> 6, c16 = slot & 63;
            size_t goff = (size_t)(b0 + row) * HSZ + c16 * 8;
            uint4 vh = __ldcg((const uint4*)(g_hbh[cur] + goff));
            uint4 vl = __ldcg((const uint4*)(g_hbl[cur] + goff));
            *(uint4*)(sm + OFF_HSH + row * WROWB + c16 * 16) = vh;
            *(uint4*)(sm + OFF_HSL + row * WROWB + c16 * 16) = vl;
        }
        __syncthreads();

        // gemm: 16(b) x 64(c) x 64(k-slice), bf16-split, fp32 frags
        float acc[8][4];
#pragma unroll
        for (int nt = 0; nt < 8; nt++)
#pragma unroll
            for (int q = 0; q < 4; q++) acc[nt][q] = 0.0f;

#pragma unroll
        for (int k16 = 0; k16 < 4; k16++) {
            const int kb = kbase + k16 * 32;
            uint32_t ah[4], al[4];
            ldsm4(sb + OFF_HSH + arow_off + kb, ah);
            ldsm4(sb + OFF_HSL + arow_off + kb, al);
            uint32_t bh[8][2], blo[8][2];
#pragma unroll
            for (int ng = 0; ng < 4; ng++) {
                uint32_t r[4];
                ldsm4(sb + OFF_WHH + (brow_base + ng * 16) * WROWB + bk_off + kb, r);
                bh[ng * 2][0] = r[0]; bh[ng * 2][1] = r[1];
                bh[ng * 2 + 1][0] = r[2]; bh[ng * 2 + 1][1] = r[3];
                ldsm4(sb + OFF_WHL + (brow_base + ng * 16) * WROWB + bk_off + kb, r);
                blo[ng * 2][0] = r[0]; blo[ng * 2][1] = r[1];
                blo[ng * 2 + 1][0] = r[2]; blo[ng * 2 + 1][1] = r[3];
            }
#pragma unroll
            for (int nt = 0; nt < 8; nt++) {
                mma16816(acc[nt], ah, bh[nt][0], bh[nt][1]);
                mma16816(acc[nt], ah, blo[nt][0], blo[nt][1]);
                mma16816(acc[nt], al, bh[nt][0], bh[nt][1]);
            }
        }

        // scatter split-K partials to red [warp][gate][b][jl]
        const int r0 = lane >> 2;
        const int cbase = (lane & 3) * 2;
#pragma unroll
        for (int nt = 0; nt < 8; nt++) {
            int gate = nt >> 1;
            int jl = (nt & 1) * 8 + cbase;
            float* p = &red[(wid * 4 + gate) * 256 + r0 * 16 + jl];
            *(float2*)p = make_float2(acc[nt][0], acc[nt][1]);
            *(float2*)(p + 8 * 16) = make_float2(acc[nt][2], acc[nt][3]);
        }
        __syncthreads();

        // reduce 8 warps + pointwise LSTM cell
        float si = 0.f, sf = 0.f, sg = 0.f, so = 0.f;
#pragma unroll
        for (int w = 0; w < 8; w++) {
            const float* rp = &red[w * 1024 + bl * 16 + jl_u];
            si += rp[0];
            sf += rp[256];
            sg += rp[512];
            so += rp[768];
        }
        float gi = si + xi + bi, gf = sf + xf + bf;
        float gg = sg + xg + bg, go = so + xo + bo;
        float iv = fast_sigmoid(gi), fv = fast_sigmoid(gf);
        float gv = fast_tanh(gg),    ov = fast_sigmoid(go);
        cc = fv * cc + iv * gv;
        float hv = ov * fast_tanh(cc);

        // publish h as bf16 split (cross-CTA), then fp32 output
        {
            __nv_bfloat16 hh = __float2bfloat16(hv);
            st_bf16_cg(&g_hbh[cur ^ 1][b * HSZ + j], hh);
            st_bf16_cg(&g_hbl[cur ^ 1][b * HSZ + j],
                       __float2bfloat16(hv - __bfloat162float(hh)));
        }
        out[((size_t)b * SEQ + t) * HSZ + j] = hv;
        if (t == SEQ - 1) {
            out[(size_t)BATCH * SEQ * HSZ + (size_t)b * HSZ + j] = hv;
            out[(size_t)BATCH * SEQ * HSZ + BATCH * HSZ + (size_t)b * HSZ + j] = cc;
        }

        // per-bt-group barrier (32 arrivals, monotonic: replay-safe)
        __syncthreads();
        if (tid == 0) {
            __threadfence();
            unsigned tk = atomicAdd(cnt, 1u) + 1u;
            unsigned target = (tk + (GRP - 1)) & ~(unsigned)(GRP - 1);
            while (*((volatile unsigned*)cnt) < target) { }
            __threadfence();
        }
        __syncthreads();
    }
}

// ---------------- launch ----------------------------------------------------
extern "C" void kernel_launch(void* const* d_in, const int* in_sizes, int n_in,
                              void* d_out, int out_size) {
    const float* x    = (const float*)d_in[0];
    const float* wih  = (const float*)d_in[1];
    const float* whh  = (const float*)d_in[2];
    const float* bias = (const float*)d_in[3];
    const float* h0   = (const float*)d_in[4];
    const float* c0   = (const float*)d_in[5];
    float* out = (float*)d_out;

    cudaFuncSetAttribute(xproj_mma, cudaFuncAttributeMaxDynamicSharedMemorySize,
                         XSMEM);
    cudaFuncSetAttribute(lstm_persist, cudaFuncAttributeMaxDynamicSharedMemorySize,
                         LSMEM);

    conv_x<<<65536, 256>>>(x);
    conv_w<<<4096, 256>>>(wih);
    conv_whh<<<4096, 256>>>(whh);
    xproj_mma<<<dim3(16, 256), 256, XSMEM>>>();
    lstm_persist<<<NCTA, 256, LSMEM>>>(bias, h0, c0, out);
}

// round 14
// speedup vs baseline: 1.9574x; 1.0045x over previous
#include <cuda_runtime.h>
#include <cuda_bf16.h>
#include <cstdint>
#include <math.h>

#define BATCH 64
#define SEQ   512
#define INSZ  512
#define HSZ   512
#define G4    2048   // 4*HSZ
#define NCTA  128
#define GRP   32     // CTAs per bt-group barrier

// ---------------- scratch (device globals; no allocation allowed) ----------
__device__ float g_xproj[(size_t)BATCH * SEQ * G4];      // x @ W_ih fp32
__device__ unsigned g_cnt4[4][32];                       // group counters
__device__ __nv_bfloat16 g_xh[(size_t)BATCH * SEQ * INSZ];   // x hi
__device__ __nv_bfloat16 g_xl[(size_t)BATCH * SEQ * INSZ];   // x lo
__device__ __nv_bfloat16 g_wth[(size_t)G4 * INSZ];           // W_ih^T hi [n][k]
__device__ __nv_bfloat16 g_wtl[(size_t)G4 * INSZ];           // W_ih^T lo
__device__ __nv_bfloat16 g_whh_h[(size_t)G4 * HSZ];          // W_hh rearranged hi [cg][k]
__device__ __nv_bfloat16 g_whh_l[(size_t)G4 * HSZ];          // W_hh rearranged lo
__device__ __nv_bfloat16 g_hbh[2][BATCH * HSZ];              // h hi ping-pong [b][j]
__device__ __nv_bfloat16 g_hbl[2][BATCH * HSZ];              // h lo ping-pong [b][j]

// ---------------- fast activations -----------------------------------------
__device__ __forceinline__ float ex2f(float x) {
    float y; asm("ex2.approx.f32 %0, %1;" : "=f"(y) : "f"(x)); return y;
}
__device__ __forceinline__ float rcpf(float x) {
    float y; asm("rcp.approx.f32 %0, %1;" : "=f"(y) : "f"(x)); return y;
}
#define LOG2E 1.4426950408889634f
__device__ __forceinline__ float fast_sigmoid(float x) {
    return rcpf(1.0f + ex2f(-x * LOG2E));
}
__device__ __forceinline__ float fast_tanh(float x) {
    float a = fabsf(x);
    float t = ex2f(-2.0f * LOG2E * a);
    float r = 1.0f - 2.0f * t * rcpf(1.0f + t);
    return copysignf(r, x);
}

// ---------------- mma.sync / ldmatrix / cp.async helpers (plain sm_103) ----
__device__ __forceinline__ uint32_t smem_u32(const void* p) {
    uint32_t a;
    asm("{ .reg .u64 t; cvta.to.shared.u64 t, %1; cvt.u32.u64 %0, t; }"
        : "=r"(a) : "l"(p));
    return a;
}
__device__ __forceinline__ void ldsm4(uint32_t addr, uint32_t r[4]) {
    asm volatile("ldmatrix.sync.aligned.m8n8.x4.shared.b16 {%0,%1,%2,%3}, [%4];"
                 : "=r"(r[0]), "=r"(r[1]), "=r"(r[2]), "=r"(r[3]) : "r"(addr));
}
__device__ __forceinline__ void mma16816(float c[4], const uint32_t a[4],
                                         uint32_t b0, uint32_t b1) {
    asm volatile(
        "mma.sync.aligned.m16n8k16.row.col.f32.bf16.bf16.f32 "
        "{%0,%1,%2,%3}, {%4,%5,%6,%7}, {%8,%9}, {%0,%1,%2,%3};"
        : "+f"(c[0]), "+f"(c[1]), "+f"(c[2]), "+f"(c[3])
        : "r"(a[0]), "r"(a[1]), "r"(a[2]), "r"(a[3]), "r"(b0), "r"(b1));
}
#define CP16(s, g) asm volatile("cp.async.cg.shared.global [%0], [%1], 16;" :: "r"(s), "l"(g))
#define CPCOMMIT() asm volatile("cp.async.commit_group;" ::: "memory")
#define CPWAIT(n)  asm volatile("cp.async.wait_group %0;" :: "n"(n) : "memory")

__device__ __forceinline__ void st_bf16_cg(__nv_bfloat16* p, __nv_bfloat16 v) {
    unsigned short u = *reinterpret_cast<unsigned short*>(&v);
    asm volatile("st.global.cg.u16 [%0], %1;" :: "l"(p), "h"(u) : "memory");
}

// ---------------- prologue conversions -------------------------------------
__global__ void conv_x(const float* __restrict__ X) {
    size_t i = (size_t)blockIdx.x * blockDim.x + threadIdx.x;
    float v = X[i];
    __nv_bfloat16 h = __float2bfloat16(v);
    g_xh[i] = h;
    g_xl[i] = __float2bfloat16(v - __bfloat162float(h));
}
__global__ void conv_w(const float* __restrict__ Wih) {
    int idx = blockIdx.x * blockDim.x + threadIdx.x;
    int k = idx >> 11, n = idx & 2047;
    float v = Wih[idx];
    __nv_bfloat16 h = __float2bfloat16(v);
    g_wth[(size_t)n * INSZ + k] = h;
    g_wtl[(size_t)n * INSZ + k] = __float2bfloat16(v - __bfloat162float(h));
}
// W_hh rearranged per-CTA contiguous: cg = jt*64 + gate*16 + jl, layout [cg][k]
__global__ void conv_whh(const float* __restrict__ Whh) {
    int idx = blockIdx.x * blockDim.x + threadIdx.x;  // k*2048 + col
    int k = idx >> 11, col = idx & 2047;
    int gate = col >> 9, rem = col & 511;
    int jt = rem >> 4, jl = rem & 15;
    size_t cg = (size_t)(jt * 64 + gate * 16 + jl);
    float v = Whh[idx];
    __nv_bfloat16 h = __float2bfloat16(v);
    g_whh_h[cg * HSZ + k] = h;
    g_whh_l[cg * HSZ + k] = __float2bfloat16(v - __bfloat162float(h));
}

// ---------------- kernel 1: x_proj via mma.sync (v2: 128x64, 2 CTA/SM) -----
#define ROWB   144              // 64 bf16 + 8 pad = 144B
#define ATILEB (128 * ROWB)     // 18432
#define BTILEB (64 * ROWB)      // 9216
#define BUFB   (2 * ATILEB + 2 * BTILEB)   // 55296: Ah, Al, Bh, Bl
#define XSMEM  (2 * BUFB)       // 110592 -> 2 CTAs/SM

__device__ __forceinline__ void stage_chunk(uint32_t sb, int buf, int ch,
                                            int m0, int n0, int tid) {
    uint32_t base = sb + buf * BUFB;
    // A hi / A lo: 128 rows x 8 chunks = 1024 slots each
#pragma unroll
    for (int s = 0; s < 4; s++) {
        int slot = tid + s * 256;
        int row = slot >> 3, c = slot & 7;
        const char* gh = (const char*)(g_xh + (size_t)(m0 + row) * INSZ + ch * 64) + c * 16;
        const char* gl = (const char*)(g_xl + (size_t)(m0 + row) * INSZ + ch * 64) + c * 16;
        CP16(base + row * ROWB + c * 16, gh);
        CP16(base + ATILEB + row * ROWB + c * 16, gl);
    }
    // B hi / B lo: 64 rows x 8 chunks = 512 slots each
#pragma unroll
    for (int s = 0; s < 2; s++) {
        int slot = tid + s * 256;
        int row = slot >> 3, c = slot & 7;
        const char* gh = (const char*)(g_wth + (size_t)(n0 + row) * INSZ + ch * 64) + c * 16;
        const char* gl = (const char*)(g_wtl + (size_t)(n0 + row) * INSZ + ch * 64) + c * 16;
        CP16(base + 2 * ATILEB + row * ROWB + c * 16, gh);
        CP16(base + 2 * ATILEB + BTILEB + row * ROWB + c * 16, gl);
    }
    CPCOMMIT();
}

__global__ __launch_bounds__(256, 2) void xproj_mma() {
    extern __shared__ char sm[];
    const uint32_t sb = smem_u32(sm);
    const int tid = threadIdx.x;
    const int wid = tid >> 5;
    const int lane = tid & 31;
    const int m0 = blockIdx.y * 128;
    const int n0 = blockIdx.x * 64;
    const int wm = (wid & 3) * 32;   // warp m offset
    const int wn = (wid >> 2) * 32;  // warp n offset (2 groups x 32)

    float acc[2][4][4];
#pragma unroll
    for (int mt = 0; mt < 2; mt++)
#pragma unroll
        for (int nt = 0; nt < 4; nt++)
#pragma unroll
            for (int q = 0; q < 4; q++) acc[mt][nt][q] = 0.0f;

    const int arow_off = (wm + (lane & 15)) * ROWB + ((lane >> 4) * 8) * 2;
    const int brow_base = wn + (lane & 7) + ((lane >> 4) << 3);
    const int bk_off = (((lane >> 3) & 1) * 8) * 2;

    stage_chunk(sb, 0, 0, m0, n0, tid);

    for (int ch = 0; ch < 8; ch++) {
        const int buf = ch & 1;
        if (ch < 7) {
            stage_chunk(sb, buf ^ 1, ch + 1, m0, n0, tid);
            CPWAIT(1);
        } else {
            CPWAIT(0);
        }
        __syncthreads();

        const uint32_t Ah = sb + buf * BUFB;
        const uint32_t Al = Ah + ATILEB;
        const uint32_t Bh = Ah + 2 * ATILEB;
        const uint32_t Bl = Bh + BTILEB;

#pragma unroll
        for (int k16 = 0; k16 < 4; k16++) {
            const int kb = k16 * 32;
            uint32_t ah[2][4], al[2][4];
#pragma unroll
            for (int mt = 0; mt < 2; mt++) {
                ldsm4(Ah + arow_off + mt * 16 * ROWB + kb, ah[mt]);
                ldsm4(Al + arow_off + mt * 16 * ROWB + kb, al[mt]);
            }
            uint32_t bh[4][2], bl[4][2];
#pragma unroll
            for (int ng = 0; ng < 2; ng++) {
                uint32_t r[4];
                ldsm4(Bh + (brow_base + ng * 16) * ROWB + bk_off + kb, r);
                bh[ng * 2][0] = r[0]; bh[ng * 2][1] = r[1];
                bh[ng * 2 + 1][0] = r[2]; bh[ng * 2 + 1][1] = r[3];
                ldsm4(Bl + (brow_base + ng * 16) * ROWB + bk_off + kb, r);
                bl[ng * 2][0] = r[0]; bl[ng * 2][1] = r[1];
                bl[ng * 2 + 1][0] = r[2]; bl[ng * 2 + 1][1] = r[3];
            }
#pragma unroll
            for (int mt = 0; mt < 2; mt++)
#pragma unroll
                for (int nt = 0; nt < 4; nt++) {
                    mma16816(acc[mt][nt], ah[mt], bh[nt][0], bh[nt][1]);
                    mma16816(acc[mt][nt], ah[mt], bl[nt][0], bl[nt][1]);
                    mma16816(acc[mt][nt], al[mt], bh[nt][0], bh[nt][1]);
                }
        }
        __syncthreads();
    }

    // epilogue: frag -> STG.64
#pragma unroll
    for (int mt = 0; mt < 2; mt++)
#pragma unroll
        for (int nt = 0; nt < 4; nt++) {
            int row = m0 + wm + mt * 16 + (lane >> 2);
            int col = n0 + wn + nt * 8 + (lane & 3) * 2;
            float* p0 = &g_xproj[(size_t)row * G4 + col];
            *(float2*)p0 = make_float2(acc[mt][nt][0], acc[mt][nt][1]);
            *(float2*)(p0 + (size_t)8 * G4) = make_float2(acc[mt][nt][2], acc[mt][nt][3]);
        }
}

// ---------------- kernel 2: persistent LSTM, mma.sync recurrence (R13) -----
#define WROWB 1040
#define OFF_WHH 0
#define OFF_WHL (OFF_WHH + 64 * WROWB)
#define OFF_HSH (OFF_WHL + 64 * WROWB)
#define OFF_HSL (OFF_HSH + 16 * WROWB)
#define OFF_RED (OFF_HSL + 16 * WROWB)
#define LSMEM   (OFF_RED + 32768)

__global__ __launch_bounds__(256, 1) void lstm_persist(
    const float* __restrict__ bias, const float* __restrict__ h0,
    const float* __restrict__ c0,   float* __restrict__ out) {
    extern __shared__ char sm[];
    const uint32_t sb = smem_u32(sm);
    float* red = (float*)(sm + OFF_RED);

    const int tid  = threadIdx.x;
    const int wid  = tid >> 5;
    const int lane = tid & 31;
    const int jt = blockIdx.x & 31, bt = blockIdx.x >> 5;
    const int j0 = jt * 16, b0 = bt * 16;
    unsigned* cnt = &g_cnt4[bt][0];

    const int bl = tid >> 4, jl_u = tid & 15;
    const int b = b0 + bl, j = j0 + jl_u;

    // init h0 as bf16 hi/lo split
    {
        float hv = h0[(size_t)b * HSZ + j];
        __nv_bfloat16 hh = __float2bfloat16(hv);
        st_bf16_cg(&g_hbh[0][b * HSZ + j], hh);
        st_bf16_cg(&g_hbl[0][b * HSZ + j],
                   __float2bfloat16(hv - __bfloat162float(hh)));
    }

    // stage W_hh slice (64 rows x 512 k, hi+lo) into smem once
    for (int it = 0; it < 16; it++) {
        int slot = tid + it * 256;
        int row = slot >> 6, c16 = slot & 63;
        size_t goff = ((size_t)(jt * 64 + row)) * HSZ + c16 * 8;
        *(uint4*)(sm + OFF_WHH + row * WROWB + c16 * 16) = *(const uint4*)(g_whh_h + goff);
        *(uint4*)(sm + OFF_WHL + row * WROWB + c16 * 16) = *(const uint4*)(g_whh_l + goff);
    }

    float cc = c0[(size_t)b * HSZ + j];
    const float bi = bias[j], bf = bias[j + HSZ];
    const float bg = bias[j + 2 * HSZ], bo = bias[j + 3 * HSZ];

    const int kbase = wid * 128;
    const int arow_off = (lane & 15) * WROWB + ((lane >> 4) * 8) * 2;
    const int brow_base = (lane & 7) + ((lane >> 4) << 3);
    const int bk_off = (((lane >> 3) & 1) * 8) * 2;

    __syncthreads();
    if (tid == 0) {
        __threadfence();
        unsigned tk = atomicAdd(cnt, 1u) + 1u;
        unsigned target = (tk + (GRP - 1)) & ~(unsigned)(GRP - 1);
        while (*((volatile unsigned*)cnt) < target) { }
        __threadfence();
    }
    __syncthreads();

    for (int t = 0; t < SEQ; t++) {
        const int cur = t & 1;

        const float* xp = g_xproj + ((size_t)b * SEQ + t) * G4 + j;
        float xi = __ldg(xp);
        float xf = __ldg(xp + HSZ);
        float xg = __ldg(xp + 2 * HSZ);
        float xo = __ldg(xp + 3 * HSZ);

#pragma unroll
        for (int it = 0; it < 4; it++) {
            int slot = tid + it * 256;
            int row = slot >> 6, c16 = slot & 63;
            size_t goff = (size_t)(b0 + row) * HSZ + c16 * 8;
            uint4 vh = __ldcg((const uint4*)(g_hbh[cur] + goff));
            uint4 vl = __ldcg((const uint4*)(g_hbl[cur] + goff));
            *(uint4*)(sm + OFF_HSH + row * WROWB + c16 * 16) = vh;
            *(uint4*)(sm + OFF_HSL + row * WROWB + c16 * 16) = vl;
        }
        __syncthreads();

        float acc[8][4];
#pragma unroll
        for (int nt = 0; nt < 8; nt++)
#pragma unroll
            for (int q = 0; q < 4; q++) acc[nt][q] = 0.0f;

#pragma unroll
        for (int k16 = 0; k16 < 4; k16++) {
            const int kb = kbase + k16 * 32;
            uint32_t ah[4], al[4];
            ldsm4(sb + OFF_HSH + arow_off + kb, ah);
            ldsm4(sb + OFF_HSL + arow_off + kb, al);
            uint32_t bh[8][2], blo[8][2];
#pragma unroll
            for (int ng = 0; ng < 4; ng++) {
                uint32_t r[4];
                ldsm4(sb + OFF_WHH + (brow_base + ng * 16) * WROWB + bk_off + kb, r);
                bh[ng * 2][0] = r[0]; bh[ng * 2][1] = r[1];
                bh[ng * 2 + 1][0] = r[2]; bh[ng * 2 + 1][1] = r[3];
                ldsm4(sb + OFF_WHL + (brow_base + ng * 16) * WROWB + bk_off + kb, r);
                blo[ng * 2][0] = r[0]; blo[ng * 2][1] = r[1];
                blo[ng * 2 + 1][0] = r[2]; blo[ng * 2 + 1][1] = r[3];
            }
#pragma unroll
            for (int nt = 0; nt < 8; nt++) {
                mma16816(acc[nt], ah, bh[nt][0], bh[nt][1]);
                mma16816(acc[nt], ah, blo[nt][0], blo[nt][1]);
                mma16816(acc[nt], al, bh[nt][0], bh[nt][1]);
            }
        }

        const int r0 = lane >> 2;
        const int cbase = (lane & 3) * 2;
#pragma unroll
        for (int nt = 0; nt < 8; nt++) {
            int gate = nt >> 1;
            int jl = (nt & 1) * 8 + cbase;
            float* p = &red[(wid * 4 + gate) * 256 + r0 * 16 + jl];
            *(float2*)p = make_float2(acc[nt][0], acc[nt][1]);
            *(float2*)(p + 8 * 16) = make_float2(acc[nt][2], acc[nt][3]);
        }
        __syncthreads();

        float si = 0.f, sf = 0.f, sg = 0.f, so = 0.f;
#pragma unroll
        for (int w = 0; w < 8; w++) {
            const float* rp = &red[w * 1024 + bl * 16 + jl_u];
            si += rp[0];
            sf += rp[256];
            sg += rp[512];
            so += rp[768];
        }
        float gi = si + xi + bi, gf = sf + xf + bf;
        float gg = sg + xg + bg, go = so + xo + bo;
        float iv = fast_sigmoid(gi), fv = fast_sigmoid(gf);
        float gv = fast_tanh(gg),    ov = fast_sigmoid(go);
        cc = fv * cc + iv * gv;
        float hv = ov * fast_tanh(cc);

        {
            __nv_bfloat16 hh = __float2bfloat16(hv);
            st_bf16_cg(&g_hbh[cur ^ 1][b * HSZ + j], hh);
            st_bf16_cg(&g_hbl[cur ^ 1][b * HSZ + j],
                       __float2bfloat16(hv - __bfloat162float(hh)));
        }
        out[((size_t)b * SEQ + t) * HSZ + j] = hv;
        if (t == SEQ - 1) {
            out[(size_t)BATCH * SEQ * HSZ + (size_t)b * HSZ + j] = hv;
            out[(size_t)BATCH * SEQ * HSZ + BATCH * HSZ + (size_t)b * HSZ + j] = cc;
        }

        __syncthreads();
        if (tid == 0) {
            __threadfence();
            unsigned tk = atomicAdd(cnt, 1u) + 1u;
            unsigned target = (tk + (GRP - 1)) & ~(unsigned)(GRP - 1);
            while (*((volatile unsigned*)cnt) < target) { }
            __threadfence();
        }
        __syncthreads();
    }
}

// ---------------- launch ----------------------------------------------------
extern "C" void kernel_launch(void* const* d_in, const int* in_sizes, int n_in,
                              void* d_out, int out_size) {
    const float* x    = (const float*)d_in[0];
    const float* wih  = (const float*)d_in[1];
    const float* whh  = (const float*)d_in[2];
    const float* bias = (const float*)d_in[3];
    const float* h0   = (const float*)d_in[4];
    const float* c0   = (const float*)d_in[5];
    float* out = (float*)d_out;

    cudaFuncSetAttribute(xproj_mma, cudaFuncAttributeMaxDynamicSharedMemorySize,
                         XSMEM);
    cudaFuncSetAttribute(lstm_persist, cudaFuncAttributeMaxDynamicSharedMemorySize,
                         LSMEM);

    conv_x<<<65536, 256>>>(x);
    conv_w<<<4096, 256>>>(wih);
    conv_whh<<<4096, 256>>>(whh);
    // 128x64 tiles: grid = (2048/64, 32768/128) = (32, 256)
    xproj_mma<<<dim3(32, 256), 256, XSMEM>>>();
    lstm_persist<<<NCTA, 256, LSMEM>>>(bias, h0, c0, out);
}